// round 14
// baseline (speedup 1.0000x reference)
#include <cuda_runtime.h>
#include <cuda_bf16.h>

#define CROP 81
#define PIX  (CROP * CROP)        // 6561
#define SPLIT 3                   // 27 rows per block
#define THREADS 128               // 123 active: 3 row-groups x 41 column-pairs

// One block = one (n,p) crop, 27 output rows. Each thread owns TWO adjacent
// columns (j0 = 2*jp, j1 = j0+1) and 9 consecutive rows (3 chunks of 3 with
// boundary horizontal-lerp carried in registers: 10 image rows / 9 outputs).
// Per window row, both columns' 4 bilinear taps come from two aligned float2
// loads covering [base, base+3]; taps are combined via per-thread constant
// 4-slot weight vectors (no selects/shuffles in the inner loop).
__global__ __launch_bounds__(THREADS)
void selectnet_kernel(const float* __restrict__ img,
                      const int*   __restrict__ label,
                      const float* __restrict__ points,
                      float*       __restrict__ out,
                      int N)
{
    const int W = 512, H = 512;
    const size_t plane = (size_t)H * W;

    // x: (wx0, wx1, bits[c0 | c1<<9 | (lx+1)<<18], 0)
    // y: (wy0, wy1, bits[y0 raw unclamped], bits[lyrow or -1])
    __shared__ float4 sxt[CROP];
    __shared__ float4 syt[CROP];

    const int q = blockIdx.x;       // n*6 + p
    const int p = q % 6;
    const int n = q / 6;
    const int t = threadIdx.x;

    if (t < CROP) {
        // ---- exact replication of reference float32 op chain ----
        const float* pt = points + (size_t)n * 18;
        float py, px;
        if (p < 5) {
            py = pt[(p + 1) * 2 + 0];
            px = pt[(p + 1) * 2 + 1];
        } else {
            py = __fdiv_rn(__fadd_rn(__fadd_rn(pt[12], pt[14]), pt[16]), 3.0f);
            px = __fdiv_rn(__fadd_rn(__fadd_rn(pt[13], pt[15]), pt[17]), 3.0f);
        }
        const float fw = 511.0f, fh = 511.0f;
        const float sx = (float)(80.0 / 511.0);   // (CROP-1)/(W-1)
        const float sy = (float)(80.0 / 512.0);   // (CROP-1)/H  (reference asymmetry)
        const float delta = __fdiv_rn(2.0f, 80.0f);

        float tx = __fadd_rn(-1.0f, __fdiv_rn(__fmul_rn(2.0f, px), fw));
        float ty = __fadd_rn(-1.0f, __fdiv_rn(__fmul_rn(2.0f, py), fh));
        float base = __fadd_rn(-1.0f, __fmul_rn((float)t, delta));
        float gx = __fadd_rn(__fmul_rn(sx, base), tx);
        float gy = __fadd_rn(__fmul_rn(sy, base), ty);
        float ix = __fmul_rn(__fmul_rn(__fadd_rn(gx, 1.0f), 0.5f), fw);
        float iy = __fmul_rn(__fmul_rn(__fadd_rn(gy, 1.0f), 0.5f), fh);

        // x table (index = j)
        float x0f = floorf(ix);
        float wx1v = ix - x0f;
        int x0 = (int)x0f, x1 = x0 + 1;
        float wx0 = (x0 >= 0 && x0 <= W - 1) ? (1.0f - wx1v) : 0.0f;
        float wx1 = (x1 >= 0 && x1 <= W - 1) ? wx1v : 0.0f;
        int c0 = min(max(x0, 0), W - 1);
        int c1 = min(max(x1, 0), W - 1);
        float xr = rintf(ix);
        int lx = (xr >= 0.0f && xr <= fw) ? (int)xr : -1;
        sxt[t] = make_float4(wx0, wx1,
                             __int_as_float(c0 | (c1 << 9) | ((lx + 1) << 18)), 0.0f);

        // y table (index = i): keep y0 UNCLAMPED (row base for tap reuse)
        float y0f = floorf(iy);
        float wy1v = iy - y0f;
        int y0 = (int)y0f, y1 = y0 + 1;
        float wy0 = (y0 >= 0 && y0 <= H - 1) ? (1.0f - wy1v) : 0.0f;
        float wy1 = (y1 >= 0 && y1 <= H - 1) ? wy1v : 0.0f;
        float yr = rintf(iy);
        int lyrow = (yr >= 0.0f && yr <= fh) ? ((int)yr) * W : -1;
        syt[t] = make_float4(wy0, wy1, __int_as_float(y0), __int_as_float(lyrow));
    }
    __syncthreads();

    if (t >= 3 * 41) return;
    const int g  = t / 41;             // 0..2 row-group
    const int jp = t - g * 41;         // 0..40 column pair
    const int j0 = 2 * jp;
    const bool has2 = (jp < 40);
    const int j1 = has2 ? j0 + 1 : j0;
    const int i0 = blockIdx.y * 27 + g * 9;

    // ---- per-thread constant x-state: 4-slot weight vectors over [base, base+3]
    float4 xt0 = sxt[j0], xt1 = sxt[j1];
    int xp0 = __float_as_int(xt0.z), xp1 = __float_as_int(xt1.z);
    const int c00 = xp0 & 511, c01 = (xp0 >> 9) & 511, lx0 = (xp0 >> 18) - 1;
    const int c10 = xp1 & 511, c11 = (xp1 >> 9) & 511, lx1 = (xp1 >> 18) - 1;
    const int base = min(c00 & ~1, 508);
    const int i00 = c00 - base, i01 = c01 - base;
    const int i10 = c10 - base, i11 = c11 - base;
    float Wa0, Wa1, Wa2, Wa3, Wb0, Wb1, Wb2, Wb3;
    Wa0 = (i00 == 0 ? xt0.x : 0.f) + (i01 == 0 ? xt0.y : 0.f);
    Wa1 = (i00 == 1 ? xt0.x : 0.f) + (i01 == 1 ? xt0.y : 0.f);
    Wa2 = (i00 == 2 ? xt0.x : 0.f) + (i01 == 2 ? xt0.y : 0.f);
    Wa3 = (i00 == 3 ? xt0.x : 0.f) + (i01 == 3 ? xt0.y : 0.f);
    Wb0 = (i10 == 0 ? xt1.x : 0.f) + (i11 == 0 ? xt1.y : 0.f);
    Wb1 = (i10 == 1 ? xt1.x : 0.f) + (i11 == 1 ? xt1.y : 0.f);
    Wb2 = (i10 == 2 ? xt1.x : 0.f) + (i11 == 2 ? xt1.y : 0.f);
    Wb3 = (i10 == 3 ? xt1.x : 0.f) + (i11 == 3 ? xt1.y : 0.f);

    const float* imgn = img   + (size_t)n * 3 * plane;
    const int*   labn = label + (size_t)n * plane;
    float* outq0  = out + (size_t)q * 3 * PIX + (size_t)i0 * CROP + j0;
    float* outq1  = out + (size_t)q * 3 * PIX + (size_t)i0 * CROP + j1;
    float* predq0 = out + (size_t)N * 6 * 3 * PIX + (size_t)q * PIX + (size_t)i0 * CROP + j0;
    float* predq1 = out + (size_t)N * 6 * 3 * PIX + (size_t)q * PIX + (size_t)i0 * CROP + j1;
    const int target = p + 1;

    // pair horizontal lerp: 2x LD.64 covering [base, base+3], 8 FMA
    auto hpair = [&](const float* rowp, float& hA, float& hB) {
        float2 f0 = __ldg((const float2*)(rowp + base));
        float2 f1 = __ldg((const float2*)(rowp + base + 2));
        hA = f0.x * Wa0 + f0.y * Wa1 + f1.x * Wa2 + f1.y * Wa3;
        hB = f0.x * Wb0 + f0.y * Wb1 + f1.x * Wb2 + f1.y * Wb3;
    };
    auto predf = [&](int lab) -> float {
        if (p < 5) return (lab == target) ? 1.0f : 0.0f;
        return (lab == 6) ? 1.0f : (lab == 7) ? 2.0f : (lab == 8) ? 3.0f : 0.0f;
    };

    const int base0 = __float_as_int(syt[i0].z);   // raw y0 of first row

    float hA2[3], hA1[3], hB2[3], hB1[3];          // carries: hl[3m-1], hl[3m]

    // ================= chunk 0 (rows 0..2, window rows 0..3) =================
    {
        float4 ya = syt[i0], yb = syt[i0 + 1], yc = syt[i0 + 2];
        bool pb = (__float_as_int(yb.z) - base0) == 1;
        bool pc = (__float_as_int(yc.z) - base0) == 2;
        int lyr0 = __float_as_int(ya.w);
        int lyr1 = __float_as_int(yb.w);
        int lyr2 = __float_as_int(yc.w);

        int ro0 = min(max(base0 + 0, 0), H - 1) << 9;
        int ro1 = min(max(base0 + 1, 0), H - 1) << 9;
        int ro2 = min(max(base0 + 2, 0), H - 1) << 9;
        int ro3 = min(max(base0 + 3, 0), H - 1) << 9;

        int laA0 = ((lx0 | lyr0) >= 0) ? __ldg(labn + lyr0 + lx0) : 0;
        int laA1 = ((lx0 | lyr1) >= 0) ? __ldg(labn + lyr1 + lx0) : 0;
        int laA2 = ((lx0 | lyr2) >= 0) ? __ldg(labn + lyr2 + lx0) : 0;
        int laB0 = ((lx1 | lyr0) >= 0) ? __ldg(labn + lyr0 + lx1) : 0;
        int laB1 = ((lx1 | lyr1) >= 0) ? __ldg(labn + lyr1 + lx1) : 0;
        int laB2 = ((lx1 | lyr2) >= 0) ? __ldg(labn + lyr2 + lx1) : 0;

        #pragma unroll
        for (int c = 0; c < 3; ++c) {
            const float* cp = imgn + (size_t)c * plane;
            float a0, b0, a1, b1, a2, b2, a3, b3;
            hpair(cp + ro0, a0, b0);
            hpair(cp + ro1, a1, b1);
            hpair(cp + ro2, a2, b2);
            hpair(cp + ro3, a3, b3);

            float oA0 = a0 * ya.x + a1 * ya.y;
            float oA1 = (pb ? a1 : a0) * yb.x + (pb ? a2 : a1) * yb.y;
            float oA2 = (pc ? a2 : a1) * yc.x + (pc ? a3 : a2) * yc.y;
            float oB0 = b0 * ya.x + b1 * ya.y;
            float oB1 = (pb ? b1 : b0) * yb.x + (pb ? b2 : b1) * yb.y;
            float oB2 = (pc ? b2 : b1) * yc.x + (pc ? b3 : b2) * yc.y;

            float* opA = outq0 + (size_t)c * PIX;
            __stcs(opA + 0 * CROP, oA0);
            __stcs(opA + 1 * CROP, oA1);
            __stcs(opA + 2 * CROP, oA2);
            if (has2) {
                float* opB = outq1 + (size_t)c * PIX;
                __stcs(opB + 0 * CROP, oB0);
                __stcs(opB + 1 * CROP, oB1);
                __stcs(opB + 2 * CROP, oB2);
            }
            hA2[c] = a2; hA1[c] = a3; hB2[c] = b2; hB1[c] = b3;
        }

        __stcs(predq0 + 0 * CROP, predf(laA0));
        __stcs(predq0 + 1 * CROP, predf(laA1));
        __stcs(predq0 + 2 * CROP, predf(laA2));
        if (has2) {
            __stcs(predq1 + 0 * CROP, predf(laB0));
            __stcs(predq1 + 1 * CROP, predf(laB1));
            __stcs(predq1 + 2 * CROP, predf(laB2));
        }
    }

    // ========== chunks m = 1,2 (rows 3m..3m+2, new window rows 3m+1..3m+3) =======
    #pragma unroll
    for (int m = 1; m < 3; ++m) {
        const int k0 = 3 * m;
        float4 ya = syt[i0 + k0], yb = syt[i0 + k0 + 1], yc = syt[i0 + k0 + 2];
        bool pa = (__float_as_int(ya.z) - base0) == k0;
        bool pb = (__float_as_int(yb.z) - base0) == k0 + 1;
        bool pc = (__float_as_int(yc.z) - base0) == k0 + 2;
        int lyr0 = __float_as_int(ya.w);
        int lyr1 = __float_as_int(yb.w);
        int lyr2 = __float_as_int(yc.w);

        int roA = min(max(base0 + k0 + 1, 0), H - 1) << 9;
        int roB = min(max(base0 + k0 + 2, 0), H - 1) << 9;
        int roC = min(max(base0 + k0 + 3, 0), H - 1) << 9;

        int laA0 = ((lx0 | lyr0) >= 0) ? __ldg(labn + lyr0 + lx0) : 0;
        int laA1 = ((lx0 | lyr1) >= 0) ? __ldg(labn + lyr1 + lx0) : 0;
        int laA2 = ((lx0 | lyr2) >= 0) ? __ldg(labn + lyr2 + lx0) : 0;
        int laB0 = ((lx1 | lyr0) >= 0) ? __ldg(labn + lyr0 + lx1) : 0;
        int laB1 = ((lx1 | lyr1) >= 0) ? __ldg(labn + lyr1 + lx1) : 0;
        int laB2 = ((lx1 | lyr2) >= 0) ? __ldg(labn + lyr2 + lx1) : 0;

        #pragma unroll
        for (int c = 0; c < 3; ++c) {
            const float* cp = imgn + (size_t)c * plane;
            float h1A, h1B, h2A, h2B, h3A, h3B;
            hpair(cp + roA, h1A, h1B);   // hl[k0+1]
            hpair(cp + roB, h2A, h2B);   // hl[k0+2]
            hpair(cp + roC, h3A, h3B);   // hl[k0+3]
            float m1A = hA1[c], m2A = hA2[c];   // hl[k0], hl[k0-1]
            float m1B = hB1[c], m2B = hB2[c];

            float oA0 = (pa ? m1A : m2A) * ya.x + (pa ? h1A : m1A) * ya.y;
            float oA1 = (pb ? h1A : m1A) * yb.x + (pb ? h2A : h1A) * yb.y;
            float oA2 = (pc ? h2A : h1A) * yc.x + (pc ? h3A : h2A) * yc.y;
            float oB0 = (pa ? m1B : m2B) * ya.x + (pa ? h1B : m1B) * ya.y;
            float oB1 = (pb ? h1B : m1B) * yb.x + (pb ? h2B : h1B) * yb.y;
            float oB2 = (pc ? h2B : h1B) * yc.x + (pc ? h3B : h2B) * yc.y;

            float* opA = outq0 + (size_t)c * PIX + (size_t)k0 * CROP;
            __stcs(opA + 0 * CROP, oA0);
            __stcs(opA + 1 * CROP, oA1);
            __stcs(opA + 2 * CROP, oA2);
            if (has2) {
                float* opB = outq1 + (size_t)c * PIX + (size_t)k0 * CROP;
                __stcs(opB + 0 * CROP, oB0);
                __stcs(opB + 1 * CROP, oB1);
                __stcs(opB + 2 * CROP, oB2);
            }
            hA2[c] = h2A; hA1[c] = h3A; hB2[c] = h2B; hB1[c] = h3B;
        }

        float* ppA = predq0 + (size_t)k0 * CROP;
        __stcs(ppA + 0 * CROP, predf(laA0));
        __stcs(ppA + 1 * CROP, predf(laA1));
        __stcs(ppA + 2 * CROP, predf(laA2));
        if (has2) {
            float* ppB = predq1 + (size_t)k0 * CROP;
            __stcs(ppB + 0 * CROP, predf(laB0));
            __stcs(ppB + 1 * CROP, predf(laB1));
            __stcs(ppB + 2 * CROP, predf(laB2));
        }
    }
}

extern "C" void kernel_launch(void* const* d_in, const int* in_sizes, int n_in,
                              void* d_out, int out_size) {
    const float* img    = (const float*)d_in[0];   // (N, 3, 512, 512) f32
    const int*   label  = (const int*)  d_in[1];   // (N, 512, 512) i32
    const float* points = (const float*)d_in[2];   // (N, 9, 2) f32
    float* out = (float*)d_out;

    int N = in_sizes[2] / 18;                      // points = N*9*2

    dim3 grid(N * 6, SPLIT);
    selectnet_kernel<<<grid, THREADS>>>(img, label, points, out, N);
}

// round 15
// speedup vs baseline: 1.4848x; 1.4848x over previous
#include <cuda_runtime.h>
#include <cuda_bf16.h>

#define CROP 81
#define PIX  (CROP * CROP)        // 6561
#define SPLIT 3                   // 27 rows per block
#define THREADS 256               // 243 active (3 groups x 81 cols)

// R12 structure (9 rows/thread, 3 chunks, boundary hl carried, __stcs) with
// explicit 2-stage software pipelining: chunk m+1's image loads are issued
// before chunk m's compute, doubling the in-flight load window.
__global__ __launch_bounds__(THREADS, 4)
void selectnet_kernel(const float* __restrict__ img,
                      const int*   __restrict__ label,
                      const float* __restrict__ points,
                      float*       __restrict__ out,
                      int N)
{
    const int W = 512, H = 512;
    const size_t plane = (size_t)H * W;

    // x: (wx0, wx1, bits[c0 | c1<<9 | (lx+1)<<18], 0)
    // y: (wy0, wy1, bits[y0 raw unclamped], bits[lyrow or -1])
    __shared__ float4 sxt[CROP];
    __shared__ float4 syt[CROP];

    const int q = blockIdx.x;       // n*6 + p
    const int p = q % 6;
    const int n = q / 6;
    const int t = threadIdx.x;

    if (t < CROP) {
        // ---- exact replication of reference float32 op chain ----
        const float* pt = points + (size_t)n * 18;
        float py, px;
        if (p < 5) {
            py = pt[(p + 1) * 2 + 0];
            px = pt[(p + 1) * 2 + 1];
        } else {
            py = __fdiv_rn(__fadd_rn(__fadd_rn(pt[12], pt[14]), pt[16]), 3.0f);
            px = __fdiv_rn(__fadd_rn(__fadd_rn(pt[13], pt[15]), pt[17]), 3.0f);
        }
        const float fw = 511.0f, fh = 511.0f;
        const float sx = (float)(80.0 / 511.0);   // (CROP-1)/(W-1)
        const float sy = (float)(80.0 / 512.0);   // (CROP-1)/H  (reference asymmetry)
        const float delta = __fdiv_rn(2.0f, 80.0f);

        float tx = __fadd_rn(-1.0f, __fdiv_rn(__fmul_rn(2.0f, px), fw));
        float ty = __fadd_rn(-1.0f, __fdiv_rn(__fmul_rn(2.0f, py), fh));
        float base = __fadd_rn(-1.0f, __fmul_rn((float)t, delta));
        float gx = __fadd_rn(__fmul_rn(sx, base), tx);
        float gy = __fadd_rn(__fmul_rn(sy, base), ty);
        float ix = __fmul_rn(__fmul_rn(__fadd_rn(gx, 1.0f), 0.5f), fw);
        float iy = __fmul_rn(__fmul_rn(__fadd_rn(gy, 1.0f), 0.5f), fh);

        // x table (index = j)
        float x0f = floorf(ix);
        float wx1v = ix - x0f;
        int x0 = (int)x0f, x1 = x0 + 1;
        float wx0 = (x0 >= 0 && x0 <= W - 1) ? (1.0f - wx1v) : 0.0f;
        float wx1 = (x1 >= 0 && x1 <= W - 1) ? wx1v : 0.0f;
        int c0 = min(max(x0, 0), W - 1);
        int c1 = min(max(x1, 0), W - 1);
        float xr = rintf(ix);
        int lx = (xr >= 0.0f && xr <= fw) ? (int)xr : -1;
        sxt[t] = make_float4(wx0, wx1,
                             __int_as_float(c0 | (c1 << 9) | ((lx + 1) << 18)), 0.0f);

        // y table (index = i): keep y0 UNCLAMPED (row base for tap reuse)
        float y0f = floorf(iy);
        float wy1v = iy - y0f;
        int y0 = (int)y0f, y1 = y0 + 1;
        float wy0 = (y0 >= 0 && y0 <= H - 1) ? (1.0f - wy1v) : 0.0f;
        float wy1 = (y1 >= 0 && y1 <= H - 1) ? wy1v : 0.0f;
        float yr = rintf(iy);
        int lyrow = (yr >= 0.0f && yr <= fh) ? ((int)yr) * W : -1;
        syt[t] = make_float4(wy0, wy1, __int_as_float(y0), __int_as_float(lyrow));
    }
    __syncthreads();

    if (t >= 3 * CROP) return;
    const int g = t / CROP;            // 0..2
    const int j = t - g * CROP;        // 0..80
    const int i0 = blockIdx.y * 27 + g * 9;

    float4 xt = sxt[j];
    int xp = __float_as_int(xt.z);
    const int c0 = xp & 511, c1 = (xp >> 9) & 511, lx = (xp >> 18) - 1;

    const float* imgn = img   + (size_t)n * 3 * plane;
    const int*   labn = label + (size_t)n * plane;
    float*       outq  = out + (size_t)q * 3 * PIX + (size_t)i0 * CROP + j;
    float*       predq = out + (size_t)N * 6 * 3 * PIX + (size_t)q * PIX + (size_t)i0 * CROP + j;
    const int target = p + 1;

    const int base0 = __float_as_int(syt[i0].z);   // raw y0 of first row

    // clamped row offsets for the 10 window rows
    int ro[10];
    #pragma unroll
    for (int k = 0; k < 10; ++k) ro[k] = min(max(base0 + k, 0), H - 1) << 9;

    // ======== load stage A: chunk0 image rows 0..3 (24 loads) ========
    float v0[24];
    #pragma unroll
    for (int c = 0; c < 3; ++c) {
        const float* cp = imgn + (size_t)c * plane;
        #pragma unroll
        for (int r = 0; r < 4; ++r) {
            v0[c * 8 + r * 2 + 0] = __ldg(cp + ro[r] + c0);
            v0[c * 8 + r * 2 + 1] = __ldg(cp + ro[r] + c1);
        }
    }
    // ======== load stage B: chunk1 image rows 4..6 (18 loads) ========
    float v1[18];
    #pragma unroll
    for (int c = 0; c < 3; ++c) {
        const float* cp = imgn + (size_t)c * plane;
        #pragma unroll
        for (int r = 0; r < 3; ++r) {
            v1[c * 6 + r * 2 + 0] = __ldg(cp + ro[4 + r] + c0);
            v1[c * 6 + r * 2 + 1] = __ldg(cp + ro[4 + r] + c1);
        }
    }

    float hp2[3], hp1[3];   // per-channel carries: hl[3m-1], hl[3m]

    // ================= chunk 0 compute (rows 0..2) =================
    {
        float4 ya = syt[i0], yb = syt[i0 + 1], yc = syt[i0 + 2];
        bool pb = (__float_as_int(yb.z) - base0) == 1;
        bool pc = (__float_as_int(yc.z) - base0) == 2;
        int lyr0 = __float_as_int(ya.w);
        int lyr1 = __float_as_int(yb.w);
        int lyr2 = __float_as_int(yc.w);
        int la0 = ((lx | lyr0) >= 0) ? __ldg(labn + lyr0 + lx) : 0;
        int la1 = ((lx | lyr1) >= 0) ? __ldg(labn + lyr1 + lx) : 0;
        int la2 = ((lx | lyr2) >= 0) ? __ldg(labn + lyr2 + lx) : 0;

        #pragma unroll
        for (int c = 0; c < 3; ++c) {
            float h0 = v0[c*8+0] * xt.x + v0[c*8+1] * xt.y;
            float h1 = v0[c*8+2] * xt.x + v0[c*8+3] * xt.y;
            float h2 = v0[c*8+4] * xt.x + v0[c*8+5] * xt.y;
            float h3 = v0[c*8+6] * xt.x + v0[c*8+7] * xt.y;

            float o0 = h0 * ya.x + h1 * ya.y;
            float o1 = (pb ? h1 : h0) * yb.x + (pb ? h2 : h1) * yb.y;
            float o2 = (pc ? h2 : h1) * yc.x + (pc ? h3 : h2) * yc.y;

            float* op = outq + (size_t)c * PIX;
            __stcs(op + 0 * CROP, o0);
            __stcs(op + 1 * CROP, o1);
            __stcs(op + 2 * CROP, o2);
            hp2[c] = h2; hp1[c] = h3;
        }

        float pr0, pr1, pr2;
        if (p < 5) {
            pr0 = (la0 == target) ? 1.0f : 0.0f;
            pr1 = (la1 == target) ? 1.0f : 0.0f;
            pr2 = (la2 == target) ? 1.0f : 0.0f;
        } else {
            pr0 = (la0 == 6) ? 1.0f : (la0 == 7) ? 2.0f : (la0 == 8) ? 3.0f : 0.0f;
            pr1 = (la1 == 6) ? 1.0f : (la1 == 7) ? 2.0f : (la1 == 8) ? 3.0f : 0.0f;
            pr2 = (la2 == 6) ? 1.0f : (la2 == 7) ? 2.0f : (la2 == 8) ? 3.0f : 0.0f;
        }
        __stcs(predq + 0 * CROP, pr0);
        __stcs(predq + 1 * CROP, pr1);
        __stcs(predq + 2 * CROP, pr2);
    }

    // ======== load stage C: chunk2 image rows 7..9 (18 loads) ========
    float v2[18];
    #pragma unroll
    for (int c = 0; c < 3; ++c) {
        const float* cp = imgn + (size_t)c * plane;
        #pragma unroll
        for (int r = 0; r < 3; ++r) {
            v2[c * 6 + r * 2 + 0] = __ldg(cp + ro[7 + r] + c0);
            v2[c * 6 + r * 2 + 1] = __ldg(cp + ro[7 + r] + c1);
        }
    }

    // ================= chunk 1 compute (rows 3..5, window rows 4..6) ============
    {
        const int k0 = 3;
        float4 ya = syt[i0 + 3], yb = syt[i0 + 4], yc = syt[i0 + 5];
        bool pa = (__float_as_int(ya.z) - base0) == k0;
        bool pb = (__float_as_int(yb.z) - base0) == k0 + 1;
        bool pc = (__float_as_int(yc.z) - base0) == k0 + 2;
        int lyr0 = __float_as_int(ya.w);
        int lyr1 = __float_as_int(yb.w);
        int lyr2 = __float_as_int(yc.w);
        int la0 = ((lx | lyr0) >= 0) ? __ldg(labn + lyr0 + lx) : 0;
        int la1 = ((lx | lyr1) >= 0) ? __ldg(labn + lyr1 + lx) : 0;
        int la2 = ((lx | lyr2) >= 0) ? __ldg(labn + lyr2 + lx) : 0;

        #pragma unroll
        for (int c = 0; c < 3; ++c) {
            float h1 = v1[c*6+0] * xt.x + v1[c*6+1] * xt.y;   // hl[4]
            float h2 = v1[c*6+2] * xt.x + v1[c*6+3] * xt.y;   // hl[5]
            float h3 = v1[c*6+4] * xt.x + v1[c*6+5] * xt.y;   // hl[6]
            float m1 = hp1[c], m2 = hp2[c];                   // hl[3], hl[2]

            float o0 = (pa ? m1 : m2) * ya.x + (pa ? h1 : m1) * ya.y;
            float o1 = (pb ? h1 : m1) * yb.x + (pb ? h2 : h1) * yb.y;
            float o2 = (pc ? h2 : h1) * yc.x + (pc ? h3 : h2) * yc.y;

            float* op = outq + (size_t)c * PIX + (size_t)k0 * CROP;
            __stcs(op + 0 * CROP, o0);
            __stcs(op + 1 * CROP, o1);
            __stcs(op + 2 * CROP, o2);
            hp2[c] = h2; hp1[c] = h3;
        }

        float pr0, pr1, pr2;
        if (p < 5) {
            pr0 = (la0 == target) ? 1.0f : 0.0f;
            pr1 = (la1 == target) ? 1.0f : 0.0f;
            pr2 = (la2 == target) ? 1.0f : 0.0f;
        } else {
            pr0 = (la0 == 6) ? 1.0f : (la0 == 7) ? 2.0f : (la0 == 8) ? 3.0f : 0.0f;
            pr1 = (la1 == 6) ? 1.0f : (la1 == 7) ? 2.0f : (la1 == 8) ? 3.0f : 0.0f;
            pr2 = (la2 == 6) ? 1.0f : (la2 == 7) ? 2.0f : (la2 == 8) ? 3.0f : 0.0f;
        }
        float* pp = predq + (size_t)k0 * CROP;
        __stcs(pp + 0 * CROP, pr0);
        __stcs(pp + 1 * CROP, pr1);
        __stcs(pp + 2 * CROP, pr2);
    }

    // ================= chunk 2 compute (rows 6..8, window rows 7..9) ============
    {
        const int k0 = 6;
        float4 ya = syt[i0 + 6], yb = syt[i0 + 7], yc = syt[i0 + 8];
        bool pa = (__float_as_int(ya.z) - base0) == k0;
        bool pb = (__float_as_int(yb.z) - base0) == k0 + 1;
        bool pc = (__float_as_int(yc.z) - base0) == k0 + 2;
        int lyr0 = __float_as_int(ya.w);
        int lyr1 = __float_as_int(yb.w);
        int lyr2 = __float_as_int(yc.w);
        int la0 = ((lx | lyr0) >= 0) ? __ldg(labn + lyr0 + lx) : 0;
        int la1 = ((lx | lyr1) >= 0) ? __ldg(labn + lyr1 + lx) : 0;
        int la2 = ((lx | lyr2) >= 0) ? __ldg(labn + lyr2 + lx) : 0;

        #pragma unroll
        for (int c = 0; c < 3; ++c) {
            float h1 = v2[c*6+0] * xt.x + v2[c*6+1] * xt.y;   // hl[7]
            float h2 = v2[c*6+2] * xt.x + v2[c*6+3] * xt.y;   // hl[8]
            float h3 = v2[c*6+4] * xt.x + v2[c*6+5] * xt.y;   // hl[9]
            float m1 = hp1[c], m2 = hp2[c];                   // hl[6], hl[5]

            float o0 = (pa ? m1 : m2) * ya.x + (pa ? h1 : m1) * ya.y;
            float o1 = (pb ? h1 : m1) * yb.x + (pb ? h2 : h1) * yb.y;
            float o2 = (pc ? h2 : h1) * yc.x + (pc ? h3 : h2) * yc.y;

            float* op = outq + (size_t)c * PIX + (size_t)k0 * CROP;
            __stcs(op + 0 * CROP, o0);
            __stcs(op + 1 * CROP, o1);
            __stcs(op + 2 * CROP, o2);
        }

        float pr0, pr1, pr2;
        if (p < 5) {
            pr0 = (la0 == target) ? 1.0f : 0.0f;
            pr1 = (la1 == target) ? 1.0f : 0.0f;
            pr2 = (la2 == target) ? 1.0f : 0.0f;
        } else {
            pr0 = (la0 == 6) ? 1.0f : (la0 == 7) ? 2.0f : (la0 == 8) ? 3.0f : 0.0f;
            pr1 = (la1 == 6) ? 1.0f : (la1 == 7) ? 2.0f : (la1 == 8) ? 3.0f : 0.0f;
            pr2 = (la2 == 6) ? 1.0f : (la2 == 7) ? 2.0f : (la2 == 8) ? 3.0f : 0.0f;
        }
        float* pp = predq + (size_t)k0 * CROP;
        __stcs(pp + 0 * CROP, pr0);
        __stcs(pp + 1 * CROP, pr1);
        __stcs(pp + 2 * CROP, pr2);
    }
}

extern "C" void kernel_launch(void* const* d_in, const int* in_sizes, int n_in,
                              void* d_out, int out_size) {
    const float* img    = (const float*)d_in[0];   // (N, 3, 512, 512) f32
    const int*   label  = (const int*)  d_in[1];   // (N, 512, 512) i32
    const float* points = (const float*)d_in[2];   // (N, 9, 2) f32
    float* out = (float*)d_out;

    int N = in_sizes[2] / 18;                      // points = N*9*2

    dim3 grid(N * 6, SPLIT);
    selectnet_kernel<<<grid, THREADS>>>(img, label, points, out, N);
}